// round 7
// baseline (speedup 1.0000x reference)
#include <cuda_runtime.h>
#include <cstdint>
#include <cstddef>

#define B_ 2
#define S_ 2048
#define D_ 64
#define H_ 8

#define TM 128
#define TN 64
#define NTHREADS 128
#define NITER (S_ / TN)

#define PQ 72   // permuted-pair layout, LDS.64 conflict-free (72 % 32 == 8)
#define PK 72
#define PV 72   // plain layout for V (raw fp32 via cp.async)
#define PP 68   // bias/P buffer, scalar-load conflict-free (R5-verified)

#define SMEM_WORDS (TM*PQ + TN*PK + TN*PV + TM*PP)
#define SMEM_BYTES (SMEM_WORDS * 4)   // 108,544 B -> 2 CTAs/SM

__device__ __forceinline__ uint32_t f2tf(float x) {
    uint32_t r;
    asm("cvt.rna.tf32.f32 %0, %1;" : "=r"(r) : "f"(x));
    return r;
}

__device__ __forceinline__ void mma_tf32(float c[4],
                                         uint32_t a0, uint32_t a1, uint32_t a2, uint32_t a3,
                                         uint32_t b0, uint32_t b1) {
    asm volatile(
        "mma.sync.aligned.m16n8k8.row.col.f32.tf32.tf32.f32 "
        "{%0,%1,%2,%3}, {%4,%5,%6,%7}, {%8,%9}, {%0,%1,%2,%3};\n"
        : "+f"(c[0]), "+f"(c[1]), "+f"(c[2]), "+f"(c[3])
        : "r"(a0), "r"(a1), "r"(a2), "r"(a3), "r"(b0), "r"(b1));
}

__device__ __forceinline__ void cp_async16(uint32_t dst_smem, const float* src) {
    asm volatile("cp.async.cg.shared.global [%0], [%1], 16;\n"
                 :: "r"(dst_smem), "l"(src));
}

__global__ void __launch_bounds__(NTHREADS, 2)
attn_bias_kernel(const float* __restrict__ x1,
                 const float* __restrict__ x2,
                 const float* __restrict__ x3,
                 const float* __restrict__ x4,
                 float* __restrict__ out) {
    const int mt = blockIdx.x;   // 0..15
    const int h  = blockIdx.y;   // 0..7
    const int b  = blockIdx.z;   // 0..1

    const int tid  = threadIdx.x;
    const int warp = tid >> 5;
    const int lane = tid & 31;
    const int r = lane >> 2;     // 0..7
    const int q = lane & 3;      // 0..3

    extern __shared__ uint32_t smem[];
    uint32_t* sQ  = smem;               // [TM][PQ] permuted-pair tf32 (x0.125)
    uint32_t* sK  = sQ + TM * PQ;       // [TN][PK] permuted-pair tf32
    uint32_t* sV  = sK + TN * PK;       // [TN][PV] RAW fp32 (truncated-tf32 in mma)
    uint32_t* sPB = sV + TN * PV;       // [TM][PP] bias fp32, then P tf32
    const float* sPBf = reinterpret_cast<const float*>(sPB);

    // ---- stage Q once: pair-permuted, pre-scaled by 0.125 (exact) ----
    // chunk (row, ch): ch = 2m+half; phys words [4*ch..4*ch+3] =
    //   logical cols {8m+2h, 8m+2h+4, 8m+2h+1, 8m+2h+5}
    const float* qbase = x1 + ((size_t)b * S_ + (size_t)mt * TM) * D_;
    #pragma unroll
    for (int j = 0; j < 16; ++j) {
        int i = j * NTHREADS + tid;
        int row = i >> 4;
        int ch  = i & 15;
        int colb = ((ch >> 1) << 3) + ((ch & 1) << 1);   // 8m + 2*half
        float2 lo = *reinterpret_cast<const float2*>(qbase + row * D_ + colb);
        float2 hi = *reinterpret_cast<const float2*>(qbase + row * D_ + colb + 4);
        uint4 o;
        o.x = f2tf(lo.x * 0.125f); o.y = f2tf(hi.x * 0.125f);
        o.z = f2tf(lo.y * 0.125f); o.w = f2tf(hi.y * 0.125f);
        *reinterpret_cast<uint4*>(sQ + row * PQ + 4 * ch) = o;
    }

    float accO[2][8][4];
    #pragma unroll
    for (int mf = 0; mf < 2; ++mf)
        #pragma unroll
        for (int n = 0; n < 8; ++n)
            #pragma unroll
            for (int j = 0; j < 4; ++j) accO[mf][n][j] = 0.0f;
    float lsum[2][2] = {{0.0f, 0.0f}, {0.0f, 0.0f}};

    const int R0 = warp * 32;
    const int R1 = warp * 32 + 16;

    // ---- per-thread staging geometry ----
    const int srow = tid >> 4;          // 0..7 : row base within 8-row groups
    const int sch  = tid & 15;          // chunk 0..15 within row
    const int scolb = ((sch >> 1) << 3) + ((sch & 1) << 1);
    // K source (pair loads), strength-reduced
    const float* kptr = x2 + (size_t)b * S_ * D_ + (size_t)srow * D_ + scolb;
    // V source (cp.async 16B chunks)
    const float* vptr = x4 + (size_t)b * S_ * D_ + (size_t)srow * D_ + sch * 4;
    const uint32_t sV_b = (uint32_t)__cvta_generic_to_shared(sV)
                        + (uint32_t)(srow * PV + sch * 4) * 4;
    // bias: warp-local rows (R5-verified pattern)
    const int brow0 = warp * 32 + (lane >> 4);
    const int bc4   = lane & 15;
    const float* bptr = x3 + (((size_t)b * H_ + h) * S_ + (size_t)mt * TM + brow0) * S_
                        + bc4 * 4;
    const uint32_t sPB_b = (uint32_t)__cvta_generic_to_shared(sPB)
                         + (uint32_t)(brow0 * PP + bc4 * 4) * 4;
    // K smem dst
    uint32_t* sKd = sK + srow * PK + 4 * sch;

    // ---- preload K registers for iteration 0 ----
    float2 klo[8], khi[8];
    #pragma unroll
    for (int j = 0; j < 8; ++j) {
        klo[j] = *reinterpret_cast<const float2*>(kptr + (size_t)(8 * j) * D_);
        khi[j] = *reinterpret_cast<const float2*>(kptr + (size_t)(8 * j) * D_ + 4);
    }

    for (int it = 0; it < NITER; ++it) {
        __syncthreads();   // prev iteration's sK/sV/sPB readers done

        // ---- group 0: bias tile cp.async (warp-local rows) ----
        #pragma unroll
        for (int j = 0; j < 16; ++j)
            cp_async16(sPB_b + (uint32_t)(2 * j * PP) * 4, bptr + (size_t)(2 * j) * S_);
        asm volatile("cp.async.commit_group;\n" ::: "memory");
        bptr += TN;

        // ---- K: STS from prefetched registers (pair-permuted, RNA tf32) ----
        #pragma unroll
        for (int j = 0; j < 8; ++j) {
            uint4 o;
            o.x = f2tf(klo[j].x); o.y = f2tf(khi[j].x);
            o.z = f2tf(klo[j].y); o.w = f2tf(khi[j].y);
            *reinterpret_cast<uint4*>(sKd + 8 * j * PK) = o;
        }

        // ---- group 1: V tile cp.async (raw fp32) ----
        #pragma unroll
        for (int j = 0; j < 8; ++j)
            cp_async16(sV_b + (uint32_t)(8 * j * PV) * 4, vptr + (size_t)(8 * j) * D_);
        asm volatile("cp.async.commit_group;\n" ::: "memory");
        vptr += TN * D_;

        __syncthreads();   // sK visible to all warps (bias, V still in flight)

        // ---- S = Q @ K^T : pair fragment loads (LDS.64) ----
        float c[2][8][4];
        #pragma unroll
        for (int mf = 0; mf < 2; ++mf)
            #pragma unroll
            for (int n = 0; n < 8; ++n)
                #pragma unroll
                for (int j = 0; j < 4; ++j) c[mf][n][j] = 0.0f;

        #pragma unroll
        for (int k = 0; k < 8; ++k) {
            uint2 qa0 = *reinterpret_cast<const uint2*>(sQ + (R0 + r)     * PQ + 8 * k + 2 * q);
            uint2 qb0 = *reinterpret_cast<const uint2*>(sQ + (R0 + r + 8) * PQ + 8 * k + 2 * q);
            uint2 qa1 = *reinterpret_cast<const uint2*>(sQ + (R1 + r)     * PQ + 8 * k + 2 * q);
            uint2 qb1 = *reinterpret_cast<const uint2*>(sQ + (R1 + r + 8) * PQ + 8 * k + 2 * q);
            #pragma unroll
            for (int n = 0; n < 8; ++n) {
                uint2 kb = *reinterpret_cast<const uint2*>(sK + (8 * n + r) * PK + 8 * k + 2 * q);
                mma_tf32(c[0][n], qa0.x, qb0.x, qa0.y, qb0.y, kb.x, kb.y);
                mma_tf32(c[1][n], qa1.x, qb1.x, qa1.y, qb1.y, kb.x, kb.y);
            }
        }

        // ---- prefetch next K tile into registers (hidden under softmax+PV) ----
        kptr += (size_t)TN * D_;
        if (it + 1 < NITER) {
            #pragma unroll
            for (int j = 0; j < 8; ++j) {
                klo[j] = *reinterpret_cast<const float2*>(kptr + (size_t)(8 * j) * D_);
                khi[j] = *reinterpret_cast<const float2*>(kptr + (size_t)(8 * j) * D_ + 4);
            }
        }

        // ---- bias ready (group 1 may still be pending) ----
        asm volatile("cp.async.wait_group 1;\n" ::: "memory");
        __syncwarp();

        // ---- logits + bias -> exp -> P (overwrite sPB, RNA tf32) ----
        #pragma unroll
        for (int mf = 0; mf < 2; ++mf) {
            const int R = (mf == 0) ? R0 : R1;
            #pragma unroll
            for (int n = 0; n < 8; ++n) {
                float2 bb0 = *reinterpret_cast<const float2*>(sPBf + (R + r) * PP + 8 * n + 2 * q);
                float2 bb1 = *reinterpret_cast<const float2*>(sPBf + (R + r + 8) * PP + 8 * n + 2 * q);
                float p0 = __expf(c[mf][n][0] + bb0.x);
                float p1 = __expf(c[mf][n][1] + bb0.y);
                float p2 = __expf(c[mf][n][2] + bb1.x);
                float p3 = __expf(c[mf][n][3] + bb1.y);
                lsum[mf][0] += p0 + p1;
                lsum[mf][1] += p2 + p3;
                uint2 w0; w0.x = f2tf(p0); w0.y = f2tf(p1);
                uint2 w1; w1.x = f2tf(p2); w1.y = f2tf(p3);
                *reinterpret_cast<uint2*>(sPB + (R + r) * PP + 8 * n + 2 * q) = w0;
                *reinterpret_cast<uint2*>(sPB + (R + r + 8) * PP + 8 * n + 2 * q) = w1;
            }
        }

        // ---- V ready + CTA-wide visibility (also covers P cross-lane reads) ----
        asm volatile("cp.async.wait_group 0;\n" ::: "memory");
        __syncthreads();

        // ---- O += P @ V (B = raw fp32 -> truncated tf32) ----
        #pragma unroll
        for (int k = 0; k < 8; ++k) {
            uint32_t a0[4], a1[4];
            a0[0] = sPB[(R0 + r) * PP + 8 * k + q];
            a0[1] = sPB[(R0 + r + 8) * PP + 8 * k + q];
            a0[2] = sPB[(R0 + r) * PP + 8 * k + q + 4];
            a0[3] = sPB[(R0 + r + 8) * PP + 8 * k + q + 4];
            a1[0] = sPB[(R1 + r) * PP + 8 * k + q];
            a1[1] = sPB[(R1 + r + 8) * PP + 8 * k + q];
            a1[2] = sPB[(R1 + r) * PP + 8 * k + q + 4];
            a1[3] = sPB[(R1 + r + 8) * PP + 8 * k + q + 4];
            #pragma unroll
            for (int n = 0; n < 8; ++n) {
                uint32_t b0 = sV[(8 * k + q) * PV + 8 * n + r];
                uint32_t b1 = sV[(8 * k + q + 4) * PV + 8 * n + r];
                mma_tf32(accO[0][n], a0[0], a0[1], a0[2], a0[3], b0, b1);
                mma_tf32(accO[1][n], a1[0], a1[1], a1[2], a1[3], b0, b1);
            }
        }
    }

    // ---- finalize: quad-reduce row sums, divide, store ----
    #pragma unroll
    for (int mf = 0; mf < 2; ++mf)
        #pragma unroll
        for (int j = 0; j < 2; ++j) {
            lsum[mf][j] += __shfl_xor_sync(0xffffffffu, lsum[mf][j], 1);
            lsum[mf][j] += __shfl_xor_sync(0xffffffffu, lsum[mf][j], 2);
        }

    float inv[2][2];
    inv[0][0] = 1.0f / lsum[0][0]; inv[0][1] = 1.0f / lsum[0][1];
    inv[1][0] = 1.0f / lsum[1][0]; inv[1][1] = 1.0f / lsum[1][1];

    float* obase = out + (((size_t)b * H_ + h) * S_ + (size_t)mt * TM) * D_;
    #pragma unroll
    for (int mf = 0; mf < 2; ++mf) {
        const int R = (mf == 0) ? R0 : R1;
        #pragma unroll
        for (int n = 0; n < 8; ++n) {
            float2 v0 = make_float2(accO[mf][n][0] * inv[mf][0], accO[mf][n][1] * inv[mf][0]);
            float2 v1 = make_float2(accO[mf][n][2] * inv[mf][1], accO[mf][n][3] * inv[mf][1]);
            *reinterpret_cast<float2*>(obase + (size_t)(R + r) * D_ + 8 * n + 2 * q) = v0;
            *reinterpret_cast<float2*>(obase + (size_t)(R + r + 8) * D_ + 8 * n + 2 * q) = v1;
        }
    }
}

extern "C" void kernel_launch(void* const* d_in, const int* in_sizes, int n_in,
                              void* d_out, int out_size) {
    (void)in_sizes; (void)n_in; (void)out_size;
    const float* x1 = (const float*)d_in[0];
    const float* x2 = (const float*)d_in[1];
    const float* x3 = (const float*)d_in[2];
    const float* x4 = (const float*)d_in[3];
    float* out = (float*)d_out;

    cudaFuncSetAttribute(attn_bias_kernel,
                         cudaFuncAttributeMaxDynamicSharedMemorySize, SMEM_BYTES);

    dim3 grid(S_ / TM, H_, B_);   // 16 x 8 x 2 = 256 CTAs
    attn_bias_kernel<<<grid, NTHREADS, SMEM_BYTES>>>(x1, x2, x3, x4, out);
}

// round 8
// speedup vs baseline: 1.3117x; 1.3117x over previous
#include <cuda_runtime.h>
#include <cstdint>
#include <cstddef>

#define B_ 2
#define S_ 2048
#define D_ 64
#define H_ 8

#define TM 128
#define TN 64
#define NTHREADS 256
#define NITER (S_ / TN)

#define PQ 68
#define PK 68
#define PV 72
#define PP 68

#define SMEM_WORDS (TM*PQ + TN*PK + TN*PV + TM*PP)
#define SMEM_BYTES (SMEM_WORDS * 4)   // 105,472 B -> 2 CTAs/SM

#define LOG2E 1.4426950408889634f

__device__ __forceinline__ uint32_t f2tf(float x) {
    uint32_t r;
    asm("cvt.rna.tf32.f32 %0, %1;" : "=r"(r) : "f"(x));
    return r;
}

__device__ __forceinline__ void mma_tf32(float c[4],
                                         uint32_t a0, uint32_t a1, uint32_t a2, uint32_t a3,
                                         uint32_t b0, uint32_t b1) {
    asm volatile(
        "mma.sync.aligned.m16n8k8.row.col.f32.tf32.tf32.f32 "
        "{%0,%1,%2,%3}, {%4,%5,%6,%7}, {%8,%9}, {%0,%1,%2,%3};\n"
        : "+f"(c[0]), "+f"(c[1]), "+f"(c[2]), "+f"(c[3])
        : "r"(a0), "r"(a1), "r"(a2), "r"(a3), "r"(b0), "r"(b1));
}

__device__ __forceinline__ void cp_async16(uint32_t dst_smem, const float* src) {
    asm volatile("cp.async.cg.shared.global [%0], [%1], 16;\n"
                 :: "r"(dst_smem), "l"(src));
}

__global__ void __launch_bounds__(NTHREADS, 2)
attn_bias_kernel(const float* __restrict__ x1,
                 const float* __restrict__ x2,
                 const float* __restrict__ x3,
                 const float* __restrict__ x4,
                 float* __restrict__ out) {
    const int mt = blockIdx.x;   // 0..15
    const int h  = blockIdx.y;   // 0..7
    const int b  = blockIdx.z;   // 0..1

    const int tid  = threadIdx.x;
    const int warp = tid >> 5;   // 0..7
    const int lane = tid & 31;
    const int r = lane >> 2;     // 0..7
    const int q = lane & 3;      // 0..3

    extern __shared__ uint32_t smem[];
    uint32_t* sQ  = smem;               // [TM][PQ] tf32, pre-scaled by 0.125*log2e
    uint32_t* sK  = sQ + TM * PQ;       // [TN][PK] tf32
    uint32_t* sV  = sK + TN * PK;       // [TN][PV] tf32
    uint32_t* sPB = sV + TN * PV;       // [TM][PP] bias fp32, then P tf32
    const float* sPBf = reinterpret_cast<const float*>(sPB);

    // ---- stage Q once (pre-scaled so logits come out in log2 units) ----
    const float* qbase = x1 + ((size_t)b * S_ + (size_t)mt * TM) * D_;
    const float qscale = 0.125f * LOG2E;
    #pragma unroll
    for (int j = 0; j < 8; ++j) {
        int i = j * NTHREADS + tid;
        int row = i >> 4;
        int c4  = i & 15;
        float4 v = *reinterpret_cast<const float4*>(qbase + row * D_ + c4 * 4);
        uint32_t* dst = sQ + row * PQ + c4 * 4;
        dst[0] = f2tf(v.x * qscale); dst[1] = f2tf(v.y * qscale);
        dst[2] = f2tf(v.z * qscale); dst[3] = f2tf(v.w * qscale);
    }

    float accO[8][4];
    #pragma unroll
    for (int n = 0; n < 8; ++n)
        #pragma unroll
        for (int j = 0; j < 4; ++j) accO[n][j] = 0.0f;
    float lsum0 = 0.0f, lsum1 = 0.0f;

    const int R = warp * 16;            // this warp's 16 rows

    // ---- per-thread staging geometry (strength-reduced pointers) ----
    // K/V: 64 rows x 16 chunks = 1024 chunks / 256 threads = 4 per thread
    const int srow = tid >> 4;          // 0..15
    const int sc4  = tid & 15;          // 0..15
    const float* kptr = x2 + (size_t)b * S_ * D_ + (size_t)srow * D_ + sc4 * 4;
    const float* vptr = x4 + (size_t)b * S_ * D_ + (size_t)srow * D_ + sc4 * 4;
    // bias: WARP-LOCAL rows [16w, 16w+16): 16 rows x 16 chunks / 32 lanes = 8 each
    const int brow0 = warp * 16 + (lane >> 4);
    const int bc4   = lane & 15;
    const float* bptr = x3 + (((size_t)b * H_ + h) * S_ + (size_t)mt * TM + brow0) * S_
                        + bc4 * 4;
    const uint32_t sPB_b = (uint32_t)__cvta_generic_to_shared(sPB)
                         + (uint32_t)(brow0 * PP + bc4 * 4) * 4;
    uint32_t* sKd = sK + srow * PK + sc4 * 4;
    uint32_t* sVd = sV + srow * PV + sc4 * 4;

    for (int t0 = 0; t0 < S_; t0 += TN) {
        __syncthreads();   // prev iteration's sK/sV/sPB readers done

        // ---- issue bias tile cp.async first (overlaps staging + QK MMA) ----
        #pragma unroll
        for (int j = 0; j < 8; ++j)
            cp_async16(sPB_b + (uint32_t)(2 * j * PP) * 4, bptr + (size_t)(2 * j) * S_);
        asm volatile("cp.async.commit_group;\n" ::: "memory");
        bptr += TN;

        // ---- stage K,V tiles (TN x 64 each), RNA tf32 ----
        #pragma unroll
        for (int j = 0; j < 4; ++j) {
            float4 kv = *reinterpret_cast<const float4*>(kptr + (size_t)(16 * j) * D_);
            uint4 ok;
            ok.x = f2tf(kv.x); ok.y = f2tf(kv.y); ok.z = f2tf(kv.z); ok.w = f2tf(kv.w);
            *reinterpret_cast<uint4*>(sKd + 16 * j * PK) = ok;
            float4 vv = *reinterpret_cast<const float4*>(vptr + (size_t)(16 * j) * D_);
            uint4 ov;
            ov.x = f2tf(vv.x); ov.y = f2tf(vv.y); ov.z = f2tf(vv.z); ov.w = f2tf(vv.w);
            *reinterpret_cast<uint4*>(sVd + 16 * j * PV) = ov;
        }
        kptr += TN * D_;
        vptr += TN * D_;
        __syncthreads();   // sK/sV ready (bias still in flight)

        // ---- S = Q @ K^T  (per warp: 16 rows x 64 cols) ----
        float c[8][4];
        #pragma unroll
        for (int n = 0; n < 8; ++n)
            #pragma unroll
            for (int j = 0; j < 4; ++j) c[n][j] = 0.0f;

        #pragma unroll
        for (int k = 0; k < 8; ++k) {
            uint32_t a0[4];
            a0[0] = sQ[(R + r) * PQ + 8 * k + q];
            a0[1] = sQ[(R + r + 8) * PQ + 8 * k + q];
            a0[2] = sQ[(R + r) * PQ + 8 * k + q + 4];
            a0[3] = sQ[(R + r + 8) * PQ + 8 * k + q + 4];
            #pragma unroll
            for (int n = 0; n < 8; ++n) {
                uint32_t b0 = sK[(8 * n + r) * PK + 8 * k + q];
                uint32_t b1 = sK[(8 * n + r) * PK + 8 * k + q + 4];
                mma_tf32(c[n], a0[0], a0[1], a0[2], a0[3], b0, b1);
            }
        }

        // ---- bias needed now; warp-local staging -> warp-local wait ----
        asm volatile("cp.async.wait_group 0;\n" ::: "memory");
        __syncwarp();

        // ---- logits + bias -> exp2 -> P (overwrite same smem slots) ----
        #pragma unroll
        for (int n = 0; n < 8; ++n) {
            float2 bb0 = *reinterpret_cast<const float2*>(sPBf + (R + r) * PP + 8 * n + 2 * q);
            float2 bb1 = *reinterpret_cast<const float2*>(sPBf + (R + r + 8) * PP + 8 * n + 2 * q);
            float p0 = exp2f(fmaf(bb0.x, LOG2E, c[n][0]));
            float p1 = exp2f(fmaf(bb0.y, LOG2E, c[n][1]));
            float p2 = exp2f(fmaf(bb1.x, LOG2E, c[n][2]));
            float p3 = exp2f(fmaf(bb1.y, LOG2E, c[n][3]));
            lsum0 += p0 + p1;
            lsum1 += p2 + p3;
            uint2 w0; w0.x = f2tf(p0); w0.y = f2tf(p1);
            uint2 w1; w1.x = f2tf(p2); w1.y = f2tf(p3);
            *reinterpret_cast<uint2*>(sPB + (R + r) * PP + 8 * n + 2 * q) = w0;
            *reinterpret_cast<uint2*>(sPB + (R + r + 8) * PP + 8 * n + 2 * q) = w1;
        }
        __syncwarp();   // each warp reads only its own 16 rows of P (cross-lane)

        // ---- O += P @ V ----
        #pragma unroll
        for (int k = 0; k < 8; ++k) {
            uint32_t a0[4];
            a0[0] = sPB[(R + r) * PP + 8 * k + q];
            a0[1] = sPB[(R + r + 8) * PP + 8 * k + q];
            a0[2] = sPB[(R + r) * PP + 8 * k + q + 4];
            a0[3] = sPB[(R + r + 8) * PP + 8 * k + q + 4];
            #pragma unroll
            for (int n = 0; n < 8; ++n) {
                uint32_t b0 = sV[(8 * k + q) * PV + 8 * n + r];
                uint32_t b1 = sV[(8 * k + q + 4) * PV + 8 * n + r];
                mma_tf32(accO[n], a0[0], a0[1], a0[2], a0[3], b0, b1);
            }
        }
    }

    // ---- finalize: quad-reduce row sums, divide, store ----
    lsum0 += __shfl_xor_sync(0xffffffffu, lsum0, 1);
    lsum0 += __shfl_xor_sync(0xffffffffu, lsum0, 2);
    lsum1 += __shfl_xor_sync(0xffffffffu, lsum1, 1);
    lsum1 += __shfl_xor_sync(0xffffffffu, lsum1, 2);
    float inv0 = 1.0f / lsum0;
    float inv1 = 1.0f / lsum1;

    float* obase = out + (((size_t)b * H_ + h) * S_ + (size_t)mt * TM) * D_;
    #pragma unroll
    for (int n = 0; n < 8; ++n) {
        float2 v0 = make_float2(accO[n][0] * inv0, accO[n][1] * inv0);
        float2 v1 = make_float2(accO[n][2] * inv1, accO[n][3] * inv1);
        *reinterpret_cast<float2*>(obase + (size_t)(R + r) * D_ + 8 * n + 2 * q) = v0;
        *reinterpret_cast<float2*>(obase + (size_t)(R + r + 8) * D_ + 8 * n + 2 * q) = v1;
    }
}

extern "C" void kernel_launch(void* const* d_in, const int* in_sizes, int n_in,
                              void* d_out, int out_size) {
    (void)in_sizes; (void)n_in; (void)out_size;
    const float* x1 = (const float*)d_in[0];
    const float* x2 = (const float*)d_in[1];
    const float* x3 = (const float*)d_in[2];
    const float* x4 = (const float*)d_in[3];
    float* out = (float*)d_out;

    cudaFuncSetAttribute(attn_bias_kernel,
                         cudaFuncAttributeMaxDynamicSharedMemorySize, SMEM_BYTES);

    dim3 grid(S_ / TM, H_, B_);   // 16 x 8 x 2 = 256 CTAs
    attn_bias_kernel<<<grid, NTHREADS, SMEM_BYTES>>>(x1, x2, x3, x4, out);
}

// round 9
// speedup vs baseline: 2.3337x; 1.7792x over previous
#include <cuda_runtime.h>
#include <cuda_fp16.h>
#include <cstdint>
#include <cstddef>

#define B_ 2
#define S_ 2048
#define D_ 64
#define H_ 8

#define TM 128
#define TN 64
#define NTHREADS 128

// pitches in 32-bit words
#define PQW 36   // Q: 64 fp16 + pad (36 % 32 == 4 -> conflict-free frags)
#define PKW 36   // K
#define PVW 36   // V^T
#define PPW 72   // bias fp32 (72 % 32 == 8 -> conflict-free float2 reads)

#define SMEM_WORDS (TM*PQW + TN*PKW + TN*PVW + TM*PPW)
#define SMEM_BYTES (SMEM_WORDS * 4)   // 73,728 B -> 2 CTAs/SM

#define LOG2E 1.4426950408889634f

__device__ __forceinline__ uint32_t pack_h2(float lo, float hi) {
    uint32_t d;   // cvt.rn.f16x2.f32 d, a, b : a -> high half, b -> low half
    asm("cvt.rn.f16x2.f32 %0, %1, %2;" : "=r"(d) : "f"(hi), "f"(lo));
    return d;
}
__device__ __forceinline__ float ex2(float x) {
    float r; asm("ex2.approx.f32 %0, %1;" : "=f"(r) : "f"(x)); return r;
}
__device__ __forceinline__ void mma_f16(float c[4],
                                        uint32_t a0, uint32_t a1, uint32_t a2, uint32_t a3,
                                        uint32_t b0, uint32_t b1) {
    asm volatile(
        "mma.sync.aligned.m16n8k16.row.col.f32.f16.f16.f32 "
        "{%0,%1,%2,%3}, {%4,%5,%6,%7}, {%8,%9}, {%0,%1,%2,%3};\n"
        : "+f"(c[0]), "+f"(c[1]), "+f"(c[2]), "+f"(c[3])
        : "r"(a0), "r"(a1), "r"(a2), "r"(a3), "r"(b0), "r"(b1));
}
__device__ __forceinline__ void cp_async16(uint32_t dst_smem, const float* src) {
    asm volatile("cp.async.cg.shared.global [%0], [%1], 16;\n"
                 :: "r"(dst_smem), "l"(src));
}

__global__ void __launch_bounds__(NTHREADS, 2)
attn_bias_kernel(const float* __restrict__ x1,
                 const float* __restrict__ x2,
                 const float* __restrict__ x3,
                 const float* __restrict__ x4,
                 float* __restrict__ out) {
    const int mt = blockIdx.x;   // 0..15
    const int h  = blockIdx.y;   // 0..7
    const int b  = blockIdx.z;   // 0..1

    const int tid  = threadIdx.x;
    const int warp = tid >> 5;
    const int lane = tid & 31;
    const int r = lane >> 2;     // groupID
    const int q = lane & 3;      // threadID-in-group

    extern __shared__ uint32_t smem[];
    uint32_t* sQ  = smem;                 // [TM][PQW]  fp16 pairs, pre-scaled
    uint32_t* sK  = sQ + TM * PQW;        // [TN][PKW]  fp16 pairs (d-packed)
    uint32_t* sVT = sK + TN * PKW;        // [64 d][PVW] fp16 pairs (t-packed, xor-swizzled)
    uint32_t* sPB = sVT + TN * PVW;       // [TM][PPW]  bias fp32
    const float* sPBf = reinterpret_cast<const float*>(sPB);

    // ---- stage Q once: fp16, pre-scaled by 0.125*log2e ----
    const float qs = 0.125f * LOG2E;
    const int srowK = tid >> 4;          // 0..7
    const int sc4   = tid & 15;          // 0..15 (16B chunk within row)
    const float* qbase = x1 + ((size_t)b * S_ + (size_t)mt * TM) * D_;
    #pragma unroll
    for (int j = 0; j < 16; ++j) {
        int row = srowK + 8 * j;
        float4 v = *reinterpret_cast<const float4*>(qbase + row * D_ + 4 * sc4);
        uint2 o;
        o.x = pack_h2(v.x * qs, v.y * qs);
        o.y = pack_h2(v.z * qs, v.w * qs);
        *reinterpret_cast<uint2*>(sQ + row * PQW + 2 * sc4) = o;
    }

    float accO[2][8][4];
    #pragma unroll
    for (int mf = 0; mf < 2; ++mf)
        #pragma unroll
        for (int n = 0; n < 8; ++n)
            #pragma unroll
            for (int j = 0; j < 4; ++j) accO[mf][n][j] = 0.0f;
    float lsum[2][2] = {{0.0f, 0.0f}, {0.0f, 0.0f}};

    const int R0 = warp * 32;            // warp's rows [R0, R0+32)

    // ---- staging pointers (strength-reduced) ----
    const float* kptr = x2 + (size_t)b * S_ * D_ + (size_t)srowK * D_ + sc4 * 4;
    // V transpose staging: thread owns t-pair tp and d-range [16*dq, 16*dq+16)
    const int tp = tid >> 2;             // 0..31
    const int dq = tid & 3;              // 0..3
    const float* vptr = x4 + (size_t)b * S_ * D_ + (size_t)(2 * tp) * D_ + 16 * dq;
    const uint32_t vxor = (uint32_t)(tp ^ (dq << 3));
    // bias: warp-local rows [32w, 32w+32)
    const int brow0 = warp * 32 + (lane >> 4);
    const int bc4   = lane & 15;
    const float* bptr = x3 + (((size_t)b * H_ + h) * S_ + (size_t)mt * TM + brow0) * S_
                        + bc4 * 4;
    const uint32_t sPB_b = (uint32_t)__cvta_generic_to_shared(sPB)
                         + (uint32_t)(brow0 * PPW + bc4 * 4) * 4;

    for (int t0 = 0; t0 < S_; t0 += TN) {
        __syncthreads();   // prev iteration's sK/sVT/sPB readers done

        // ---- bias tile cp.async first (overlaps staging + QK) ----
        #pragma unroll
        for (int j = 0; j < 16; ++j)
            cp_async16(sPB_b + (uint32_t)(2 * j * PPW) * 4, bptr + (size_t)(2 * j) * S_);
        asm volatile("cp.async.commit_group;\n" ::: "memory");
        bptr += TN;

        // ---- stage K: fp16 pairs along d, row-major [t][d] ----
        #pragma unroll
        for (int j = 0; j < 8; ++j) {
            int row = srowK + 8 * j;
            float4 v = *reinterpret_cast<const float4*>(kptr + (size_t)(8 * j) * D_);
            uint2 o;
            o.x = pack_h2(v.x, v.y);
            o.y = pack_h2(v.z, v.w);
            *reinterpret_cast<uint2*>(sK + row * PKW + 2 * sc4) = o;
        }
        kptr += (size_t)TN * D_;

        // ---- stage V transposed: VT[d][t], fp16 pairs along t, xor-swizzled ----
        #pragma unroll
        for (int jj = 0; jj < 4; ++jj) {
            float4 va = *reinterpret_cast<const float4*>(vptr + 4 * jj);
            float4 vb = *reinterpret_cast<const float4*>(vptr + D_ + 4 * jj);
            int d0 = 16 * dq + 4 * jj;
            sVT[(d0 + 0) * PVW + ((uint32_t)0 ^ vxor)] = pack_h2(va.x, vb.x);
            sVT[(d0 + 1) * PVW + vxor]                 = pack_h2(va.y, vb.y);
            sVT[(d0 + 2) * PVW + vxor]                 = pack_h2(va.z, vb.z);
            sVT[(d0 + 3) * PVW + vxor]                 = pack_h2(va.w, vb.w);
        }
        vptr += (size_t)TN * D_;
        __syncthreads();   // sK/sVT visible (bias still in flight)

        // ---- QK: S = Q @ K^T, fp16 m16n8k16, 4 k-steps over d ----
        float c[2][8][4];
        #pragma unroll
        for (int mf = 0; mf < 2; ++mf)
            #pragma unroll
            for (int n = 0; n < 8; ++n)
                #pragma unroll
                for (int j = 0; j < 4; ++j) c[mf][n][j] = 0.0f;

        #pragma unroll
        for (int k = 0; k < 4; ++k) {
            uint32_t a[2][4];
            #pragma unroll
            for (int mf = 0; mf < 2; ++mf) {
                const uint32_t* qrow0 = sQ + (R0 + 16 * mf + r) * PQW + 8 * k + q;
                const uint32_t* qrow1 = sQ + (R0 + 16 * mf + r + 8) * PQW + 8 * k + q;
                a[mf][0] = qrow0[0];
                a[mf][1] = qrow1[0];
                a[mf][2] = qrow0[4];
                a[mf][3] = qrow1[4];
            }
            #pragma unroll
            for (int n = 0; n < 8; ++n) {
                const uint32_t* krow = sK + (8 * n + r) * PKW + 8 * k + q;
                uint32_t b0 = krow[0];
                uint32_t b1 = krow[4];
                mma_f16(c[0][n], a[0][0], a[0][1], a[0][2], a[0][3], b0, b1);
                mma_f16(c[1][n], a[1][0], a[1][1], a[1][2], a[1][3], b0, b1);
            }
        }

        // ---- bias ready; warp-local wait ----
        asm volatile("cp.async.wait_group 0;\n" ::: "memory");
        __syncwarp();

        // ---- softmax: exp in log2 domain, P packed to fp16 REGISTERS ----
        uint32_t pk[2][8][2];
        #pragma unroll
        for (int mf = 0; mf < 2; ++mf) {
            const int R = R0 + 16 * mf;
            #pragma unroll
            for (int n = 0; n < 8; ++n) {
                float2 bb0 = *reinterpret_cast<const float2*>(sPBf + (R + r) * PPW + 8 * n + 2 * q);
                float2 bb1 = *reinterpret_cast<const float2*>(sPBf + (R + r + 8) * PPW + 8 * n + 2 * q);
                float p0 = ex2(fmaf(bb0.x, LOG2E, c[mf][n][0]));
                float p1 = ex2(fmaf(bb0.y, LOG2E, c[mf][n][1]));
                float p2 = ex2(fmaf(bb1.x, LOG2E, c[mf][n][2]));
                float p3 = ex2(fmaf(bb1.y, LOG2E, c[mf][n][3]));
                lsum[mf][0] += p0 + p1;
                lsum[mf][1] += p2 + p3;
                pk[mf][n][0] = pack_h2(p0, p1);   // row r,   t = 8n+2q, 2q+1
                pk[mf][n][1] = pack_h2(p2, p3);   // row r+8
            }
        }

        // ---- PV: O += P @ V ; A = P from registers, B = VT from smem ----
        #pragma unroll
        for (int n = 0; n < 8; ++n) {
            const int d = 8 * n + r;
            const uint32_t f = (uint32_t)(((d >> 4) & 3) << 3);
            const uint32_t* vrow = sVT + d * PVW;
            #pragma unroll
            for (int k = 0; k < 4; ++k) {
                uint32_t b0 = vrow[(uint32_t)(8 * k + q) ^ f];
                uint32_t b1 = vrow[(uint32_t)(8 * k + q + 4) ^ f];
                mma_f16(accO[0][n], pk[0][2*k][0], pk[0][2*k][1],
                                    pk[0][2*k+1][0], pk[0][2*k+1][1], b0, b1);
                mma_f16(accO[1][n], pk[1][2*k][0], pk[1][2*k][1],
                                    pk[1][2*k+1][0], pk[1][2*k+1][1], b0, b1);
            }
        }
    }

    // ---- finalize: quad-reduce row sums, divide, store ----
    #pragma unroll
    for (int mf = 0; mf < 2; ++mf)
        #pragma unroll
        for (int j = 0; j < 2; ++j) {
            lsum[mf][j] += __shfl_xor_sync(0xffffffffu, lsum[mf][j], 1);
            lsum[mf][j] += __shfl_xor_sync(0xffffffffu, lsum[mf][j], 2);
        }

    float inv[2][2];
    inv[0][0] = 1.0f / lsum[0][0]; inv[0][1] = 1.0f / lsum[0][1];
    inv[1][0] = 1.0f / lsum[1][0]; inv[1][1] = 1.0f / lsum[1][1];

    float* obase = out + (((size_t)b * H_ + h) * S_ + (size_t)mt * TM) * D_;
    #pragma unroll
    for (int mf = 0; mf < 2; ++mf) {
        const int R = R0 + 16 * mf;
        #pragma unroll
        for (int n = 0; n < 8; ++n) {
            float2 v0 = make_float2(accO[mf][n][0] * inv[mf][0], accO[mf][n][1] * inv[mf][0]);
            float2 v1 = make_float2(accO[mf][n][2] * inv[mf][1], accO[mf][n][3] * inv[mf][1]);
            *reinterpret_cast<float2*>(obase + (size_t)(R + r) * D_ + 8 * n + 2 * q) = v0;
            *reinterpret_cast<float2*>(obase + (size_t)(R + r + 8) * D_ + 8 * n + 2 * q) = v1;
        }
    }
}

extern "C" void kernel_launch(void* const* d_in, const int* in_sizes, int n_in,
                              void* d_out, int out_size) {
    (void)in_sizes; (void)n_in; (void)out_size;
    const float* x1 = (const float*)d_in[0];
    const float* x2 = (const float*)d_in[1];
    const float* x3 = (const float*)d_in[2];
    const float* x4 = (const float*)d_in[3];
    float* out = (float*)d_out;

    cudaFuncSetAttribute(attn_bias_kernel,
                         cudaFuncAttributeMaxDynamicSharedMemorySize, SMEM_BYTES);

    dim3 grid(S_ / TM, H_, B_);   // 16 x 8 x 2 = 256 CTAs
    attn_bias_kernel<<<grid, NTHREADS, SMEM_BYTES>>>(x1, x2, x3, x4, out);
}